// round 8
// baseline (speedup 1.0000x reference)
#include <cuda_runtime.h>
#include <cuda_bf16.h>
#include <cstdint>

#define KCODES   512
#define DDIM     64
#define HWSZ     4096
#define NPTS     131072
#define TPTS     128
#define NTILES   1024
#define ZQ_ELEMS 8388608
#define NTHREADS 512

#define STRCB    144          // bytes per codebook row (128B data + 16B pad)
#define STRZ     65           // floats per z row (pad -> conflict-free)

// ---- SMEM layout (bytes) ----
#define OFF_CB   0                         // bf16 cb, k-permuted: 512*144 = 73728
#define OFF_ZF   73728                     // f32 z [128][65]            = 33280
#define OFF_EN   107008                    // f32 ||e||^2 [512]          = 2048
#define OFF_ZN   109056                    // f32 ||z||^2 [128]          = 512
#define OFF_THR  109568                    // f32 thr [128]              = 512
#define OFF_PM   110080                    // f32 partial mins [2][128]  = 1024
#define OFF_KEY  111104                    // u64 best key [128]         = 1024
#define OFF_IDX  112128                    // i32 idx [128]              = 512
#define OFF_EMX  112640                    // i32 emax bits              = 16
#define OFF_LST  112656                    // u32 cand list [16][64]     = 4096
#define SMEM_BYTES 116752

__device__ __forceinline__ void mma16816(float* d, const uint32_t* a,
                                         uint32_t b0, uint32_t b1) {
    asm volatile("mma.sync.aligned.m16n8k16.row.col.f32.bf16.bf16.f32 "
                 "{%0,%1,%2,%3}, {%4,%5,%6,%7}, {%8,%9}, {%0,%1,%2,%3};"
                 : "+f"(d[0]), "+f"(d[1]), "+f"(d[2]), "+f"(d[3])
                 : "r"(a[0]), "r"(a[1]), "r"(a[2]), "r"(a[3]), "r"(b0), "r"(b1));
}
__device__ __forceinline__ uint32_t packbf(float lo, float hi) {
    uint32_t r;
    asm("cvt.rn.bf16x2.f32 %0, %1, %2;" : "=r"(r) : "f"(hi), "f"(lo));
    return r;
}

// exact fp32 rescore: channel-sequential fma chain (same order as proven kernels)
__device__ __forceinline__ void rescore(const float* zf, const float* s_zn,
                                        const float* s_en, unsigned long long* s_key,
                                        const float* cb, int p, int k) {
    const float* er = cb + (size_t)k * DDIM;
    const float* zp = zf + p * STRZ;
    float dot = 0.f;
    #pragma unroll 8
    for (int c = 0; c < DDIM; c++) dot = fmaf(zp[c], __ldg(er + c), dot);
    float dd = s_zn[p] + s_en[k] - 2.f * dot;
    unsigned long long key = ((unsigned long long)__float_as_uint(dd) << 32) | (unsigned)k;
    atomicMin(&s_key[p], key);
}

// one quarter of the tile: 16 rows x 128 cols, K=64 (16 mma frags x 4 ksteps)
__device__ __forceinline__ void run_mma(float acc[16][4], const uint32_t ra[4][4],
                                        const char* cbb, int n0, int g, int tig) {
    #pragma unroll
    for (int f = 0; f < 16; f++)
        #pragma unroll
        for (int e = 0; e < 4; e++) acc[f][e] = 0.f;
    #pragma unroll
    for (int j = 0; j < 4; j++) {
        #pragma unroll
        for (int f = 0; f < 16; f++) {
            uint2 bb = *(const uint2*)(cbb + (size_t)(n0 + f * 8 + g) * STRCB
                                           + j * 32 + tig * 8);
            mma16816(acc[f], ra[j], bb.x, bb.y);
        }
    }
}

// mode: 0 = z_q only; 1 = z_q + indices-as-float appended; 2 = indices only
__global__ void __launch_bounds__(NTHREADS, 1)
vq_kernel(const float* __restrict__ z_e,
          const float* __restrict__ cb,
          float* __restrict__ out,
          int mode, int nctas)
{
    extern __shared__ char smem[];
    float* zf    = (float*)(smem + OFF_ZF);
    float* s_en  = (float*)(smem + OFF_EN);
    float* s_zn  = (float*)(smem + OFF_ZN);
    float* s_thr = (float*)(smem + OFF_THR);
    float* s_pm  = (float*)(smem + OFF_PM);
    unsigned long long* s_key = (unsigned long long*)(smem + OFF_KEY);
    int*   s_idx = (int*)(smem + OFF_IDX);
    int*   s_emx = (int*)(smem + OFF_EMX);

    const int tid  = threadIdx.x;
    const int w    = tid >> 5;
    const int lane = tid & 31;
    const int g    = lane >> 2;          // row-in-group / B col
    const int tig  = lane & 3;
    const int m0   = (w & 7) * 16;       // warp's 16-row base
    const int hc   = w >> 3;             // warp's 256-col half
    const unsigned lmlt = (1u << lane) - 1u;
    uint32_t* wlist = (uint32_t*)(smem + OFF_LST) + w * 64;

    if (tid == 0) *s_emx = 0;
    __syncthreads();

    // ---- Stage codebook once: bf16 k-permuted rows + fp32 ||e||^2 + emax ----
    {
        const int k = tid;
        const float4* e4 = (const float4*)(cb + (size_t)k * DDIM);
        char* row = smem + OFF_CB + (size_t)k * STRCB;
        float nrm = 0.f, amx = 0.f;
        #pragma unroll
        for (int c4 = 0; c4 < 16; c4++) {
            float4 a = e4[c4];
            float vv[4] = { a.x, a.y, a.z, a.w };
            #pragma unroll
            for (int q = 0; q < 4; q++) {
                int c = 4 * c4 + q;
                float v = vv[q];
                nrm = fmaf(v, v, nrm);
                amx = fmaxf(amx, fabsf(v));
                int j = c >> 4, kk = c & 15;
                int mm = (kk & 7) >> 1, h = kk >> 3, b = kk & 1;
                *(__nv_bfloat16*)(row + j * 32 + mm * 8 + h * 4 + b * 2) =
                    __float2bfloat16(v);
            }
        }
        s_en[k] = nrm;
        atomicMax(s_emx, __float_as_int(amx));
    }
    __syncthreads();
    const float emax = __int_as_float(*s_emx);

    for (int tile = blockIdx.x; tile < NTILES; tile += nctas) {
        __syncthreads();   // prior tile's consumers of zf/s_key done

        // ---- Stage z tile fp32 -> zf[p][c] (padded) ----
        {
            const float* zg = z_e + (size_t)(tile >> 5) * (DDIM * HWSZ)
                                  + (size_t)(tile & 31) * TPTS;
            #pragma unroll
            for (int it = 0; it < 4; it++) {
                int i4 = it * NTHREADS + tid;          // 0..2047
                int c = i4 >> 5, p = (i4 & 31) * 4;
                float4 v = *(const float4*)(zg + (size_t)c * HWSZ + p);
                zf[(p + 0) * STRZ + c] = v.x;
                zf[(p + 1) * STRZ + c] = v.y;
                zf[(p + 2) * STRZ + c] = v.z;
                zf[(p + 3) * STRZ + c] = v.w;
            }
        }
        __syncthreads();

        // ---- znorm + sum|z| per point (exact-order fma chains) ----
        float sab = 0.f;
        if (tid < 128) {
            const float* zp = zf + tid * STRZ;
            float zn = 0.f;
            #pragma unroll 8
            for (int c = 0; c < DDIM; c++) {
                float v = zp[c];
                zn = fmaf(v, v, zn);
                sab += fabsf(v);
            }
            s_zn[tid] = zn;
        }

        // ---- Build register A-fragments (bf16) for this warp's 16 rows ----
        uint32_t ra[4][4];
        #pragma unroll
        for (int j = 0; j < 4; j++) {
            const float* r0 = zf + (m0 + g) * STRZ + 16 * j + 2 * tig;
            const float* r1 = zf + (m0 + g + 8) * STRZ + 16 * j + 2 * tig;
            ra[j][0] = packbf(r0[0], r0[1]);
            ra[j][1] = packbf(r1[0], r1[1]);
            ra[j][2] = packbf(r0[8], r0[9]);
            ra[j][3] = packbf(r1[8], r1[9]);
        }

        // ---- Pass 1: mma, track per-row min of t = ||e||^2 - 2 dot1 ----
        float rm0 = 3.402823e38f, rm1 = 3.402823e38f;
        #pragma unroll
        for (int nb = 0; nb < 2; nb++) {
            float acc[16][4];
            int n0 = hc * 256 + nb * 128;
            run_mma(acc, ra, smem + OFF_CB, n0, g, tig);
            #pragma unroll
            for (int f = 0; f < 16; f++) {
                int k0 = n0 + f * 8 + 2 * tig;
                float e0 = s_en[k0], e1 = s_en[k0 + 1];
                rm0 = fminf(rm0, fminf(e0 - 2.f * acc[f][0], e1 - 2.f * acc[f][1]));
                rm1 = fminf(rm1, fminf(e0 - 2.f * acc[f][2], e1 - 2.f * acc[f][3]));
            }
        }
        rm0 = fminf(rm0, __shfl_xor_sync(0xFFFFFFFFu, rm0, 1));
        rm0 = fminf(rm0, __shfl_xor_sync(0xFFFFFFFFu, rm0, 2));
        rm1 = fminf(rm1, __shfl_xor_sync(0xFFFFFFFFu, rm1, 1));
        rm1 = fminf(rm1, __shfl_xor_sync(0xFFFFFFFFu, rm1, 2));
        if (tig == 0) {
            s_pm[hc * 128 + m0 + g]     = rm0;
            s_pm[hc * 128 + m0 + g + 8] = rm1;
        }
        __syncthreads();

        // ---- Threshold: guaranteed window around approx min ----
        if (tid < 128) {
            float tmin = fminf(s_pm[tid], s_pm[128 + tid]);
            float S = sab * emax;                 // >= sum |z_c||e_c|
            s_thr[tid] = tmin + fmaf(0.018f, S, 1.5e-4f);   // 2B with margin
            s_key[tid] = ~0ull;
        }
        __syncthreads();

        // ---- Pass 2: mma again, collect candidates, exact rescore ----
        {
            const float thrA = s_thr[m0 + g];
            const float thrB = s_thr[m0 + g + 8];
            int cnt = 0;
            #pragma unroll
            for (int nb = 0; nb < 2; nb++) {
                float acc[16][4];
                int n0 = hc * 256 + nb * 128;
                run_mma(acc, ra, smem + OFF_CB, n0, g, tig);
                #pragma unroll
                for (int f = 0; f < 16; f++) {
                    int k0 = n0 + f * 8 + 2 * tig;
                    float e0 = s_en[k0], e1 = s_en[k0 + 1];
                    float t00 = e0 - 2.f * acc[f][0];
                    float t01 = e1 - 2.f * acc[f][1];
                    float t10 = e0 - 2.f * acc[f][2];
                    float t11 = e1 - 2.f * acc[f][3];
                    #pragma unroll
                    for (int e = 0; e < 4; e++) {
                        bool cond; int p, kk;
                        if (e == 0)      { cond = (t00 <= thrA); p = m0 + g;     kk = k0;     }
                        else if (e == 1) { cond = (t01 <= thrA); p = m0 + g;     kk = k0 + 1; }
                        else if (e == 2) { cond = (t10 <= thrB); p = m0 + g + 8; kk = k0;     }
                        else             { cond = (t11 <= thrB); p = m0 + g + 8; kk = k0 + 1; }
                        unsigned msk = __ballot_sync(0xFFFFFFFFu, cond);
                        if (cond) {
                            int pos = cnt + __popc(msk & lmlt);
                            if (pos < 64) wlist[pos] = ((unsigned)p << 9) | (unsigned)kk;
                            else rescore(zf, s_zn, s_en, s_key, cb, p, kk);
                        }
                        cnt += __popc(msk);
                    }
                }
            }
            if (cnt > 64) cnt = 64;
            for (int i = lane; i < cnt; i += 32) {
                uint32_t en_ = wlist[i];
                rescore(zf, s_zn, s_en, s_key, cb, (int)(en_ >> 9), (int)(en_ & 511));
            }
        }
        __syncthreads();

        if (tid < 128) s_idx[tid] = (int)(s_key[tid] & 0xFFFFFFFFull);
        __syncthreads();

        // ---- Emit ----
        if (mode == 2) {
            if (tid < 128) ((int*)out)[tile * 128 + tid] = s_idx[tid];
        } else {
            float4* out4 = (float4*)out + (size_t)tile * 2048;
            const float4* cb4 = (const float4*)cb;
            #pragma unroll
            for (int it = 0; it < 4; it++) {
                int i4 = it * NTHREADS + tid;
                int p = i4 >> 4, c4 = i4 & 15;
                out4[i4] = cb4[(size_t)s_idx[p] * 16 + c4];
            }
            if (mode == 1 && tid < 128)
                out[ZQ_ELEMS + tile * 128 + tid] = (float)s_idx[tid];
        }
    }
}

extern "C" void kernel_launch(void* const* d_in, const int* in_sizes, int n_in,
                              void* d_out, int out_size)
{
    const float* z_e = (const float*)d_in[0];
    const float* cb  = (const float*)d_in[1];
    float* out = (float*)d_out;

    int mode;
    if (out_size >= ZQ_ELEMS + NPTS) mode = 1;
    else if (out_size >= ZQ_ELEMS)   mode = 0;
    else                             mode = 2;

    int sms = 0;
    cudaDeviceGetAttribute(&sms, cudaDevAttrMultiProcessorCount, 0);
    if (sms <= 0) sms = 148;

    cudaFuncSetAttribute(vq_kernel, cudaFuncAttributeMaxDynamicSharedMemorySize, SMEM_BYTES);
    vq_kernel<<<sms, NTHREADS, SMEM_BYTES>>>(z_e, cb, out, mode, sms);
}

// round 9
// speedup vs baseline: 1.0952x; 1.0952x over previous
#include <cuda_runtime.h>
#include <cuda_bf16.h>
#include <cstdint>

#define KCODES   512
#define DDIM     64
#define HWSZ     4096
#define NPTS     131072
#define TPTS     128
#define NTILES   1024
#define ZQ_ELEMS 8388608
#define NTHREADS 512

#define STRZ     65           // floats per z row (pad -> conflict-free)

// ---- SMEM layout (bytes) ----
// cb frag-major: [64 nblk][4 j][32 lane][8B]  = 65536
#define OFF_CB   0
#define OFF_ZF   65536                     // f32 z [128][65]            = 33280
#define OFF_EN   98816                     // f32 ||e||^2 [512]          = 2048
#define OFF_ZN   100864                    // f32 ||z||^2 [128]          = 512
#define OFF_THR  101376                    // f32 thr [128]              = 512
#define OFF_PM   101888                    // f32 partial mins [2][128]  = 1024
#define OFF_KEY  102912                    // u64 best key [128]         = 1024
#define OFF_IDX  103936                    // i32 idx [128]              = 512
#define OFF_EMX  104448                    // i32 emax bits              = 16
#define OFF_LST  104464                    // u32 cand list [16][64]     = 4096
#define SMEM_BYTES 108560

__device__ __forceinline__ void mma16816(float* d, const uint32_t* a,
                                         uint32_t b0, uint32_t b1) {
    asm volatile("mma.sync.aligned.m16n8k16.row.col.f32.bf16.bf16.f32 "
                 "{%0,%1,%2,%3}, {%4,%5,%6,%7}, {%8,%9}, {%0,%1,%2,%3};"
                 : "+f"(d[0]), "+f"(d[1]), "+f"(d[2]), "+f"(d[3])
                 : "r"(a[0]), "r"(a[1]), "r"(a[2]), "r"(a[3]), "r"(b0), "r"(b1));
}
__device__ __forceinline__ uint32_t packbf(float lo, float hi) {
    uint32_t r;
    asm("cvt.rn.bf16x2.f32 %0, %1, %2;" : "=r"(r) : "f"(hi), "f"(lo));
    return r;
}

// exact fp32 rescore: channel-sequential fma chain (same order as proven kernels)
__device__ __forceinline__ void rescore(const float* zf, const float* s_zn,
                                        const float* s_en, unsigned long long* s_key,
                                        const float* cb, int p, int k) {
    const float* er = cb + (size_t)k * DDIM;
    const float* zp = zf + p * STRZ;
    float dot = 0.f;
    #pragma unroll 8
    for (int c = 0; c < DDIM; c++) dot = fmaf(zp[c], __ldg(er + c), dot);
    float dd = s_zn[p] + s_en[k] - 2.f * dot;
    unsigned long long key = ((unsigned long long)__float_as_uint(dd) << 32) | (unsigned)k;
    atomicMin(&s_key[p], key);
}

// one quarter: 16 rows x 128 cols, K=64. B loads are frag-major: coalesced,
// conflict-free LDS.64 at (Bblk*4+j)*256 + lane*8.
__device__ __forceinline__ void run_mma(float acc[16][4], const uint32_t ra[4][4],
                                        const char* cbb, int Bbase, int lane) {
    #pragma unroll
    for (int f = 0; f < 16; f++)
        #pragma unroll
        for (int e = 0; e < 4; e++) acc[f][e] = 0.f;
    const char* base = cbb + ((size_t)Bbase * 4) * 256 + lane * 8;
    #pragma unroll
    for (int j = 0; j < 4; j++) {
        #pragma unroll
        for (int f = 0; f < 16; f++) {
            uint2 bb = *(const uint2*)(base + (f * 4 + j) * 256);
            mma16816(acc[f], ra[j], bb.x, bb.y);
        }
    }
}

// mode: 0 = z_q only; 1 = z_q + indices-as-float appended; 2 = indices only
__global__ void __launch_bounds__(NTHREADS, 1)
vq_kernel(const float* __restrict__ z_e,
          const float* __restrict__ cb,
          float* __restrict__ out,
          int mode, int nctas)
{
    extern __shared__ char smem[];
    float* zf    = (float*)(smem + OFF_ZF);
    float* s_en  = (float*)(smem + OFF_EN);
    float* s_zn  = (float*)(smem + OFF_ZN);
    float* s_thr = (float*)(smem + OFF_THR);
    float* s_pm  = (float*)(smem + OFF_PM);
    unsigned long long* s_key = (unsigned long long*)(smem + OFF_KEY);
    int*   s_idx = (int*)(smem + OFF_IDX);
    int*   s_emx = (int*)(smem + OFF_EMX);

    const int tid  = threadIdx.x;
    const int w    = tid >> 5;
    const int lane = tid & 31;
    const int g    = lane >> 2;
    const int tig  = lane & 3;
    const int m0   = (w & 7) * 16;       // warp's 16-row base
    const int hc   = w >> 3;             // warp's 256-col half
    const unsigned lmlt = (1u << lane) - 1u;
    uint32_t* wlist = (uint32_t*)(smem + OFF_LST) + w * 64;

    if (tid == 0) *s_emx = 0;
    __syncthreads();

    // ---- Stage codebook once: frag-major bf16 + fp32 ||e||^2 + emax ----
    // code k -> nblk B=k>>3, col g=k&7. Lane slot = g*4+tig; within the 8B:
    // h*4+b*2 holds channel c = j*16 + 2*tig + b + 8*h  (PTX m16n8k16 B frag).
    {
        const int k = tid;
        const float4* e4 = (const float4*)(cb + (size_t)k * DDIM);
        char* base = smem + OFF_CB + (size_t)(k >> 3) * 1024 + (k & 7) * 32;
        float nrm = 0.f, amx = 0.f;
        #pragma unroll
        for (int c4 = 0; c4 < 16; c4++) {
            float4 a = e4[c4];
            float vv[4] = { a.x, a.y, a.z, a.w };
            #pragma unroll
            for (int q = 0; q < 4; q++) {
                int c = 4 * c4 + q;
                float v = vv[q];
                nrm = fmaf(v, v, nrm);
                amx = fmaxf(amx, fabsf(v));
                int j = c >> 4, kk = c & 15;
                int tg = (kk & 7) >> 1, h = kk >> 3, b = kk & 1;
                *(__nv_bfloat16*)(base + j * 256 + tg * 8 + h * 4 + b * 2) =
                    __float2bfloat16(v);
            }
        }
        s_en[k] = nrm;
        atomicMax(s_emx, __float_as_int(amx));
    }
    __syncthreads();
    const float emax = __int_as_float(*s_emx);

    for (int tile = blockIdx.x; tile < NTILES; tile += nctas) {
        __syncthreads();   // prior tile's consumers of zf/s_key done

        // ---- Stage z tile fp32 -> zf[p][c] (padded) ----
        {
            const float* zg = z_e + (size_t)(tile >> 5) * (DDIM * HWSZ)
                                  + (size_t)(tile & 31) * TPTS;
            #pragma unroll
            for (int it = 0; it < 4; it++) {
                int i4 = it * NTHREADS + tid;          // 0..2047
                int c = i4 >> 5, p = (i4 & 31) * 4;
                float4 v = *(const float4*)(zg + (size_t)c * HWSZ + p);
                zf[(p + 0) * STRZ + c] = v.x;
                zf[(p + 1) * STRZ + c] = v.y;
                zf[(p + 2) * STRZ + c] = v.z;
                zf[(p + 3) * STRZ + c] = v.w;
            }
        }
        __syncthreads();

        // ---- znorm + sum|z| per point (exact-order fma chains) ----
        float sab = 0.f;
        if (tid < 128) {
            const float* zp = zf + tid * STRZ;
            float zn = 0.f;
            #pragma unroll 8
            for (int c = 0; c < DDIM; c++) {
                float v = zp[c];
                zn = fmaf(v, v, zn);
                sab += fabsf(v);
            }
            s_zn[tid] = zn;
        }

        // ---- Build register A-fragments (bf16) for this warp's 16 rows ----
        uint32_t ra[4][4];
        #pragma unroll
        for (int j = 0; j < 4; j++) {
            const float* r0 = zf + (m0 + g) * STRZ + 16 * j + 2 * tig;
            const float* r1 = zf + (m0 + g + 8) * STRZ + 16 * j + 2 * tig;
            ra[j][0] = packbf(r0[0], r0[1]);
            ra[j][1] = packbf(r1[0], r1[1]);
            ra[j][2] = packbf(r0[8], r0[9]);
            ra[j][3] = packbf(r1[8], r1[9]);
        }

        // ---- Pass 1: mma, track per-row min of t = ||e||^2 - 2 dot1 ----
        float rm0 = 3.402823e38f, rm1 = 3.402823e38f;
        #pragma unroll
        for (int nb = 0; nb < 2; nb++) {
            float acc[16][4];
            int Bbase = hc * 32 + nb * 16;
            run_mma(acc, ra, smem + OFF_CB, Bbase, lane);
            #pragma unroll
            for (int f = 0; f < 16; f++) {
                int k0 = (Bbase + f) * 8 + 2 * tig;
                float e0 = s_en[k0], e1 = s_en[k0 + 1];
                rm0 = fminf(rm0, fminf(e0 - 2.f * acc[f][0], e1 - 2.f * acc[f][1]));
                rm1 = fminf(rm1, fminf(e0 - 2.f * acc[f][2], e1 - 2.f * acc[f][3]));
            }
        }
        rm0 = fminf(rm0, __shfl_xor_sync(0xFFFFFFFFu, rm0, 1));
        rm0 = fminf(rm0, __shfl_xor_sync(0xFFFFFFFFu, rm0, 2));
        rm1 = fminf(rm1, __shfl_xor_sync(0xFFFFFFFFu, rm1, 1));
        rm1 = fminf(rm1, __shfl_xor_sync(0xFFFFFFFFu, rm1, 2));
        if (tig == 0) {
            s_pm[hc * 128 + m0 + g]     = rm0;
            s_pm[hc * 128 + m0 + g + 8] = rm1;
        }
        __syncthreads();

        // ---- Threshold: guaranteed window around approx min ----
        if (tid < 128) {
            float tmin = fminf(s_pm[tid], s_pm[128 + tid]);
            float S = sab * emax;                 // >= sum |z_c||e_c|
            s_thr[tid] = tmin + fmaf(0.018f, S, 1.5e-4f);   // 2B with margin
            s_key[tid] = ~0ull;
        }
        __syncthreads();

        // ---- Pass 2: mma again, collect candidates, exact rescore ----
        {
            const float thrA = s_thr[m0 + g];
            const float thrB = s_thr[m0 + g + 8];
            int cnt = 0;
            #pragma unroll
            for (int nb = 0; nb < 2; nb++) {
                float acc[16][4];
                int Bbase = hc * 32 + nb * 16;
                run_mma(acc, ra, smem + OFF_CB, Bbase, lane);
                #pragma unroll
                for (int f = 0; f < 16; f++) {
                    int k0 = (Bbase + f) * 8 + 2 * tig;
                    float e0 = s_en[k0], e1 = s_en[k0 + 1];
                    float t00 = e0 - 2.f * acc[f][0];
                    float t01 = e1 - 2.f * acc[f][1];
                    float t10 = e0 - 2.f * acc[f][2];
                    float t11 = e1 - 2.f * acc[f][3];
                    #pragma unroll
                    for (int e = 0; e < 4; e++) {
                        bool cond; int p, kk;
                        if (e == 0)      { cond = (t00 <= thrA); p = m0 + g;     kk = k0;     }
                        else if (e == 1) { cond = (t01 <= thrA); p = m0 + g;     kk = k0 + 1; }
                        else if (e == 2) { cond = (t10 <= thrB); p = m0 + g + 8; kk = k0;     }
                        else             { cond = (t11 <= thrB); p = m0 + g + 8; kk = k0 + 1; }
                        unsigned msk = __ballot_sync(0xFFFFFFFFu, cond);
                        if (cond) {
                            int pos = cnt + __popc(msk & lmlt);
                            if (pos < 64) wlist[pos] = ((unsigned)p << 9) | (unsigned)kk;
                            else rescore(zf, s_zn, s_en, s_key, cb, p, kk);
                        }
                        cnt += __popc(msk);
                    }
                }
            }
            if (cnt > 64) cnt = 64;
            for (int i = lane; i < cnt; i += 32) {
                uint32_t en_ = wlist[i];
                rescore(zf, s_zn, s_en, s_key, cb, (int)(en_ >> 9), (int)(en_ & 511));
            }
        }
        __syncthreads();

        if (tid < 128) s_idx[tid] = (int)(s_key[tid] & 0xFFFFFFFFull);
        __syncthreads();

        // ---- Emit ----
        if (mode == 2) {
            if (tid < 128) ((int*)out)[tile * 128 + tid] = s_idx[tid];
        } else {
            float4* out4 = (float4*)out + (size_t)tile * 2048;
            const float4* cb4 = (const float4*)cb;
            #pragma unroll
            for (int it = 0; it < 4; it++) {
                int i4 = it * NTHREADS + tid;
                int p = i4 >> 4, c4 = i4 & 15;
                out4[i4] = cb4[(size_t)s_idx[p] * 16 + c4];
            }
            if (mode == 1 && tid < 128)
                out[ZQ_ELEMS + tile * 128 + tid] = (float)s_idx[tid];
        }
    }
}

extern "C" void kernel_launch(void* const* d_in, const int* in_sizes, int n_in,
                              void* d_out, int out_size)
{
    const float* z_e = (const float*)d_in[0];
    const float* cb  = (const float*)d_in[1];
    float* out = (float*)d_out;

    int mode;
    if (out_size >= ZQ_ELEMS + NPTS) mode = 1;
    else if (out_size >= ZQ_ELEMS)   mode = 0;
    else                             mode = 2;

    int sms = 0;
    cudaDeviceGetAttribute(&sms, cudaDevAttrMultiProcessorCount, 0);
    if (sms <= 0) sms = 148;

    cudaFuncSetAttribute(vq_kernel, cudaFuncAttributeMaxDynamicSharedMemorySize, SMEM_BYTES);
    vq_kernel<<<sms, NTHREADS, SMEM_BYTES>>>(z_e, cb, out, mode, sms);
}

// round 10
// speedup vs baseline: 1.3854x; 1.2650x over previous
#include <cuda_runtime.h>
#include <cstdint>

#define KCODES   512
#define DDIM     64
#define HWSZ     4096
#define NPTS     131072
#define TPTS     128            // points per tile
#define NTILES   (NPTS / TPTS)  // 1024
#define ZQ_ELEMS 8388608
#define NTHREADS 512

// dynamic SMEM layout (bytes):
//  s_cb : u64[64][256]  pair-transposed codebook {e[2p][c], e[2p+1][c]}  131072
//  s_z2 : u64[64][128]  duplicated z {v,v} per (channel, point)          65536
//  s_en : f32[512]      ||e_k||^2 (pair u64 view: {even, odd})           2048
//  s_zn : f32[128]                                                       512
//  s_pm : f32[2][128]   per-half best dist                               1024
//  s_pk : i32[2][128]   per-half best k                                  1024
//  s_idx: i32[128]                                                       512
#define OFF_CB   0
#define OFF_Z    131072
#define OFF_EN   196608
#define OFF_ZN   198656
#define OFF_PM   199168
#define OFF_PK   200192
#define OFF_IDX  201216
#define SMEM_BYTES 201728

__device__ __forceinline__ unsigned long long pk2(float lo, float hi) {
    unsigned long long r;
    asm("mov.b64 %0, {%1,%2};" : "=l"(r) : "f"(lo), "f"(hi));
    return r;
}
__device__ __forceinline__ float2 unpk2(unsigned long long v) {
    float2 f;
    asm("mov.b64 {%0,%1}, %2;" : "=f"(f.x), "=f"(f.y) : "l"(v));
    return f;
}
// packed dual-fp32 FMA (sm_100+; PTX-only, ptxas never auto-fuses)
__device__ __forceinline__ void ffma2(unsigned long long& d,
                                      unsigned long long a,
                                      unsigned long long b) {
    asm("fma.rn.f32x2 %0, %1, %2, %0;" : "+l"(d) : "l"(a), "l"(b));
}

// mode: 0 = z_q only; 1 = z_q + indices-as-float appended; 2 = indices only (int32)
__global__ void __launch_bounds__(NTHREADS, 1)
vq_kernel(const float* __restrict__ z_e,
          const float* __restrict__ cb,
          float* __restrict__ out,
          int mode, int nctas)
{
    extern __shared__ char smem[];
    unsigned long long* s_cb = (unsigned long long*)(smem + OFF_CB);
    unsigned long long* s_z2 = (unsigned long long*)(smem + OFF_Z);
    unsigned long long* s_en = (unsigned long long*)(smem + OFF_EN);
    float* s_zn  = (float*)(smem + OFF_ZN);
    float* s_pm  = (float*)(smem + OFF_PM);
    int*   s_pk  = (int*)  (smem + OFF_PK);
    int*   s_idx = (int*)  (smem + OFF_IDX);

    const int tid  = threadIdx.x;
    const int lane = tid & 31;
    const int w    = tid >> 5;
    const int hc   = w >> 3;          // code half: pairs [hc*128, hc*128+128)
    const int pw   = w & 7;           // point group of 16
    const int ps   = lane & 1;        // 8-pt sub-block within group
    const int cs   = lane >> 1;       // 16 code-subgroups x 4 pairs
    const int ptb  = pw * 16 + ps * 8;

    // ---- Stage codebook once: pair-transposed + per-code norms (1 code/thread) ----
    {
        const int code = tid;                       // 0..511
        const float4* e0 = (const float4*)(cb + (size_t)code * DDIM);
        float* s_cbf = (float*)s_cb;
        float* s_enf = (float*)s_en;
        const int p    = code >> 1;
        const int half = code & 1;                  // lo = even code, hi = odd
        float nrm = 0.f;
        #pragma unroll
        for (int c4 = 0; c4 < 16; c4++) {
            float4 a = e0[c4];
            nrm += a.x*a.x + a.y*a.y + a.z*a.z + a.w*a.w;
            int c = 4 * c4;
            s_cbf[((c+0)*256 + p)*2 + half] = a.x;
            s_cbf[((c+1)*256 + p)*2 + half] = a.y;
            s_cbf[((c+2)*256 + p)*2 + half] = a.z;
            s_cbf[((c+3)*256 + p)*2 + half] = a.w;
        }
        s_enf[code] = nrm;
    }

    for (int tile = blockIdx.x; tile < NTILES; tile += nctas) {
        // ---- Stage z tile, duplicated {v,v}. Tile never straddles batch b. ----
        {
            const float* zg = z_e + (size_t)(tile >> 5) * (DDIM * HWSZ)
                                  + (size_t)(tile & 31) * TPTS;
            #pragma unroll
            for (int it = 0; it < 4; it++) {
                int i4 = it * NTHREADS + tid;   // 0..2047 float4 slots
                int c  = i4 >> 5;               // channel
                int p  = (i4 & 31) * 4;         // point base
                float4 v = *(const float4*)(zg + (size_t)c * HWSZ + p);
                ulonglong2* dst = (ulonglong2*)(s_z2 + c * 128 + p);
                dst[0] = make_ulonglong2(pk2(v.x, v.x), pk2(v.y, v.y));
                dst[1] = make_ulonglong2(pk2(v.z, v.z), pk2(v.w, v.w));
            }
        }
        __syncthreads();

        // ---- znorm per point (exact channel-sequential fma chain) ----
        if (tid < 128) {
            const float* zc = (const float*)s_z2;   // low half at 2*(c*128+pt)
            float zn = 0.f;
            #pragma unroll 8
            for (int c = 0; c < 64; c++) {
                float v = zc[(c * 128 + tid) * 2];
                zn = fmaf(v, v, zn);
            }
            s_zn[tid] = zn;
        }
        __syncthreads();

        // ---- Main sweep: 8 points x 4 pairs per thread, 2 chunks of 64 pairs ----
        float bestD[8]; int bestK[8];
        #pragma unroll
        for (int m = 0; m < 8; m++) { bestD[m] = 3.402823e38f; bestK[m] = 0; }
        float znm[8];
        #pragma unroll
        for (int m = 0; m < 8; m++) znm[m] = s_zn[ptb + m];

        #pragma unroll
        for (int chunk = 0; chunk < 2; chunk++) {
            unsigned long long acc[8][4];
            #pragma unroll
            for (int m = 0; m < 8; m++)
                #pragma unroll
                for (int j = 0; j < 4; j++) acc[m][j] = 0ull;

            const unsigned long long* pz = s_z2 + ptb;
            const unsigned long long* pc = s_cb + hc * 128 + chunk * 64 + cs * 4;

            #pragma unroll 8
            for (int c = 0; c < 64; c++) {
                const ulonglong2* zrow = (const ulonglong2*)pz;
                ulonglong2 za = zrow[0], zb = zrow[1], zc2 = zrow[2], zd = zrow[3];
                unsigned long long z2r[8] = { za.x, za.y, zb.x, zb.y,
                                              zc2.x, zc2.y, zd.x, zd.y };
                const ulonglong2* crow = (const ulonglong2*)pc;
                ulonglong2 c01 = crow[0], c23 = crow[1];
                unsigned long long cbp[4] = { c01.x, c01.y, c23.x, c23.y };
                #pragma unroll
                for (int m = 0; m < 8; m++)
                    #pragma unroll
                    for (int j = 0; j < 4; j++)
                        ffma2(acc[m][j], z2r[m], cbp[j]);
                pz += 128;        // next channel, z row
                pc += 256;        // next channel, cb row
            }
            // chunk epilogue: distances + running argmin (ascending code order)
            #pragma unroll
            for (int j = 0; j < 4; j++) {
                int pr = hc * 128 + chunk * 64 + cs * 4 + j;
                float2 en = unpk2(s_en[pr]);
                int k0 = 2 * pr;
                #pragma unroll
                for (int m = 0; m < 8; m++) {
                    float2 d = unpk2(acc[m][j]);
                    float dd = znm[m] + en.x - 2.f * d.x;
                    if (dd < bestD[m]) { bestD[m] = dd; bestK[m] = k0; }
                    dd = znm[m] + en.y - 2.f * d.y;
                    if (dd < bestD[m]) { bestD[m] = dd; bestK[m] = k0 + 1; }
                }
            }
        }

        // ---- Reduce across the 16 code-subgroups (xor strides keep ps fixed) ----
        #pragma unroll
        for (int m = 0; m < 8; m++) {
            float d = bestD[m]; int k = bestK[m];
            #pragma unroll
            for (int s = 2; s < 32; s <<= 1) {
                float od = __shfl_xor_sync(0xFFFFFFFFu, d, s);
                int   ok = __shfl_xor_sync(0xFFFFFFFFu, k, s);
                if (od < d || (od == d && ok < k)) { d = od; k = ok; }
            }
            if (cs == 0) {
                s_pm[hc * 128 + ptb + m] = d;
                s_pk[hc * 128 + ptb + m] = k;
            }
        }
        __syncthreads();

        // ---- Merge the two code halves (tie -> half 0 = lower k) ----
        if (tid < 128) {
            float d = s_pm[tid]; int k = s_pk[tid];
            float od = s_pm[128 + tid]; int ok = s_pk[128 + tid];
            if (od < d) { d = od; k = ok; }
            s_idx[tid] = k;
        }
        __syncthreads();

        // ---- Emit ----
        if (mode == 2) {
            if (tid < 128) ((int*)out)[tile * 128 + tid] = s_idx[tid];
        } else {
            float4* out4 = (float4*)out + (size_t)tile * 2048;
            const float4* cb4 = (const float4*)cb;
            #pragma unroll
            for (int it = 0; it < 4; it++) {
                int i4 = it * NTHREADS + tid;
                int p  = i4 >> 4;
                int c4 = i4 & 15;
                out4[i4] = cb4[(size_t)s_idx[p] * 16 + c4];
            }
            if (mode == 1 && tid < 128)
                out[ZQ_ELEMS + tile * 128 + tid] = (float)s_idx[tid];
        }
        // next iteration's first __syncthreads separates s_idx readers from rewriters
    }
}

extern "C" void kernel_launch(void* const* d_in, const int* in_sizes, int n_in,
                              void* d_out, int out_size)
{
    const float* z_e = (const float*)d_in[0];
    const float* cb  = (const float*)d_in[1];
    float* out = (float*)d_out;

    int mode;
    if (out_size >= ZQ_ELEMS + NPTS) mode = 1;
    else if (out_size >= ZQ_ELEMS)   mode = 0;
    else                             mode = 2;

    int sms = 0;
    cudaDeviceGetAttribute(&sms, cudaDevAttrMultiProcessorCount, 0);
    if (sms <= 0) sms = 148;

    cudaFuncSetAttribute(vq_kernel, cudaFuncAttributeMaxDynamicSharedMemorySize, SMEM_BYTES);
    vq_kernel<<<sms, NTHREADS, SMEM_BYTES>>>(z_e, cb, out, mode, sms);
}